// round 17
// baseline (speedup 1.0000x reference)
#include <cuda_runtime.h>
#include <cuda_fp16.h>
#include <cstdint>
#include <cstddef>

#define BATCH   16384
#define HID     2048
#define NLAYER  8
#define PIN     25

#define MT      128
#define NT      128
#define KC      64                  // 64 fp16 k-values = 128B per row
#define NCH     (HID / KC)          // 32
#define NSTG    3
#define ABYTES  (MT * 128)          // 16384
#define BBYTES  (NT * 128)          // 16384
#define STGB    (ABYTES + BBYTES)   // 32768
#define DYNSMEM (NSTG * STGB + 1024) // 99328  (x2 CTAs = 194.5KB/SM)
#define NTHR    256
#define MBLKS   (BATCH / MT)        // 128
#define NBLKS   (HID / NT)          // 16

#define WT_BLKS  256                // 32 per layer, 64 cols each
#define EMB_BLKS 512                // 32 rows x 2048 cols each
#define PRE_BLKS (WT_BLKS + EMB_BLKS)

// ---------------- device scratch (allocation-free) ----------------
__device__ float  g_h0[(size_t)BATCH * HID];     // exact fp32 activations
__device__ float  g_h1[(size_t)BATCH * HID];
__device__ __half g_ta0[(size_t)BATCH * HID];    // fp16-rounded MMA copies
__device__ __half g_ta1[(size_t)BATCH * HID];
__device__ __half g_wt[(size_t)NLAYER * HID * HID];  // W^T fp16 [l][n][k]
__device__ float  g_patch[(size_t)BATCH * PIN];
__device__ int    g_flags[NLAYER * MBLKS];       // n-tiles done per (layer, m-block)
__device__ int    g_eflag[MBLKS];                // embed blocks done per m-block (4 each)
__device__ int    g_wflag[NLAYER];               // wtrans blocks done per layer (32 each)

// ---------------- helpers ----------------
__device__ __forceinline__ uint32_t smem_u32(const void* p) {
    uint32_t a;
    asm("{ .reg .u64 t; cvta.to.shared.u64 t, %1; cvt.u32.u64 %0, t; }" : "=r"(a) : "l"(p));
    return a;
}

__device__ __forceinline__ void cp_async16(uint32_t s, const void* g) {
    asm volatile("cp.async.cg.shared.global [%0], [%1], 16;" :: "r"(s), "l"(g) : "memory");
}

__device__ __forceinline__ void prefetch_l2(const void* g) {
    asm volatile("prefetch.global.L2 [%0];" :: "l"(g));
}

__device__ __forceinline__ void mma_f16(float* c, const uint32_t* a, const uint32_t* b) {
    asm volatile(
        "mma.sync.aligned.m16n8k16.row.col.f32.f16.f16.f32 "
        "{%0,%1,%2,%3}, {%4,%5,%6,%7}, {%8,%9}, {%0,%1,%2,%3};"
        : "+f"(c[0]), "+f"(c[1]), "+f"(c[2]), "+f"(c[3])
        : "r"(a[0]), "r"(a[1]), "r"(a[2]), "r"(a[3]), "r"(b[0]), "r"(b[1]));
}

#define LDSM4(r0, r1, r2, r3, addr) \
    asm volatile("ldmatrix.sync.aligned.m8n8.x4.shared.b16 {%0,%1,%2,%3}, [%4];" \
        : "=r"(r0), "=r"(r1), "=r"(r2), "=r"(r3) : "r"(addr))

#define MBARRIER_INIT(addr, count) \
    asm volatile("mbarrier.init.shared.b64 [%0], %1;" \
        :: "r"((uint32_t)(addr)), "r"((uint32_t)(count)) : "memory")

#define MBARRIER_ARRIVE(addr) \
    asm volatile("mbarrier.arrive.shared.b64 _, [%0];" \
        :: "r"((uint32_t)(addr)) : "memory")

#define CPASYNC_MBAR_ARRIVE(addr) \
    asm volatile("cp.async.mbarrier.arrive.noinc.shared.b64 [%0];" \
        :: "r"((uint32_t)(addr)) : "memory")

#define MBARRIER_WAIT_PARITY(mbar_smem_addr, phase_parity) do { \
    uint32_t _mbar = (uint32_t)(mbar_smem_addr); \
    uint32_t _parity = (uint32_t)(phase_parity); \
    uint32_t _done; \
    asm volatile( \
        "{\n\t.reg .pred p;\n\t" \
        "mbarrier.try_wait.parity.acquire.cta.shared::cta.b64 p, [%1], %2;\n\t" \
        "selp.b32 %0, 1, 0, p;\n\t}" \
        : "=r"(_done) : "r"(_mbar), "r"(_parity) : "memory"); \
    if (!_done) { \
        asm volatile( \
            "{\n\t.reg .pred P1;\n\t" \
            "WAIT_LOOP_%=:\n\t" \
            "mbarrier.try_wait.parity.acquire.cta.shared::cta.b64 P1, [%0], %1, 0x989680;\n\t" \
            "@P1 bra.uni WAIT_DONE_%=;\n\t" \
            "bra.uni WAIT_LOOP_%=;\n\t" \
            "WAIT_DONE_%=:\n\t}" \
            :: "r"(_mbar), "r"(_parity) : "memory"); \
    } \
} while (0)

// producer-side wait: post-wait accesses are cp.async only (async proxy) -> relaxed
#define MBARRIER_WAIT_PARITY_RELAXED(mbar_smem_addr, phase_parity) do { \
    uint32_t _mbar = (uint32_t)(mbar_smem_addr); \
    uint32_t _parity = (uint32_t)(phase_parity); \
    uint32_t _done; \
    asm volatile( \
        "{\n\t.reg .pred p;\n\t" \
        "mbarrier.try_wait.parity.relaxed.cta.shared::cta.b64 p, [%1], %2, 0x989680;\n\t" \
        "selp.b32 %0, 1, 0, p;\n\t}" \
        : "=r"(_done) : "r"(_mbar), "r"(_parity) : "memory"); \
    if (!_done) { \
        asm volatile( \
            "{\n\t.reg .pred P1;\n\t" \
            "WAIT_LOOP_%=:\n\t" \
            "mbarrier.try_wait.parity.relaxed.cta.shared::cta.b64 P1, [%0], %1, 0x989680;\n\t" \
            "@P1 bra.uni WAIT_DONE_%=;\n\t" \
            "bra.uni WAIT_LOOP_%=;\n\t" \
            "WAIT_DONE_%=:\n\t}" \
            :: "r"(_mbar), "r"(_parity) : "memory"); \
    } \
} while (0)

// ============================================================
// Kernel 1: find agent, extract 5x5 patch (pad -1). Block 0 also
// zeroes all cross-kernel flags (kernel completes before mega launch).
// ============================================================
__global__ void __launch_bounds__(256) patch_kernel(const float* __restrict__ x) {
    if (blockIdx.x == 0) {
        for (int i = threadIdx.x; i < NLAYER * MBLKS; i += 256) g_flags[i] = 0;
        if (threadIdx.x < MBLKS) g_eflag[threadIdx.x] = 0;
        if (threadIdx.x < NLAYER) g_wflag[threadIdx.x] = 0;
    }
    int w = threadIdx.x >> 5, lane = threadIdx.x & 31;
    int b = blockIdx.x * 8 + w;
    const float* xb = x + (size_t)b * 1024;
    int found = 0;
#pragma unroll
    for (int s = 0; s < 32; s++)
        if (xb[s * 32 + lane] == 3.0f) found = s * 32 + lane;
#pragma unroll
    for (int off = 16; off; off >>= 1)
        found = max(found, __shfl_xor_sync(0xffffffffu, found, off));
    int row = found >> 5, col = found & 31;
    if (lane < PIN) {
        int r = row + lane / 5 - 2;
        int c = col + lane % 5 - 2;
        float v = (r < 0 || r > 31 || c < 0 || c > 31) ? -1.0f : xb[r * 32 + c];
        g_patch[(size_t)b * PIN + lane] = v;
    }
}

// ============================================================
// MEGA kernel: wtrans blocks | embed blocks | all-layer gemm tiles.
// Cross-role ordering via device flags (all waits point at smaller bids).
// ============================================================
__global__ void __launch_bounds__(NTHR, 2) mega_kernel(const float* __restrict__ eW,
                                                       const float* __restrict__ ebias,
                                                       const float* __restrict__ Wall,
                                                       const float* __restrict__ bias_all) {
    extern __shared__ char dynsmem[];
    int tid = threadIdx.x;
    int bid = blockIdx.x;

    // ---------------- role: wtrans ----------------
    if (bid < WT_BLKS) {
        int l = bid >> 5, q = bid & 31;              // 64 cols per block
        float* t = (float*)dynsmem;                   // [32][33]
        const float* W = Wall + (size_t)l * HID * HID;
        __half* WT = g_wt + (size_t)l * HID * HID;
        int tx = tid & 31, ty = tid >> 5;             // ty 0..7
        for (int n0 = q * 64; n0 < q * 64 + 64; n0 += 32) {
            for (int k0 = 0; k0 < HID; k0 += 32) {
#pragma unroll
                for (int i = 0; i < 4; i++)
                    t[(ty + i * 8) * 33 + tx] = W[(size_t)(k0 + ty + i * 8) * HID + n0 + tx];
                __syncthreads();
#pragma unroll
                for (int i = 0; i < 4; i++)
                    WT[(size_t)(n0 + ty + i * 8) * HID + k0 + tx] =
                        __float2half_rn(t[tx * 33 + ty + i * 8]);
                __syncthreads();
            }
        }
        __threadfence();
        __syncthreads();
        if (tid == 0) atomicAdd(&g_wflag[l], 1);
        return;
    }

    // ---------------- role: embed ----------------
    if (bid < PRE_BLKS) {
        int ebk = bid - WT_BLKS;                      // 0..511, 32 rows each
        int mb = ebk * 32;
        float* sp = (float*)dynsmem;                  // [32][25]
        for (int i = tid; i < 32 * PIN; i += 256)
            sp[i] = g_patch[(size_t)mb * PIN + i];
        __syncthreads();
        int tc = tid & 31, sg = tid >> 5;             // 4 cols x 4 rows per thread
        for (int nb = 0; nb < 16; nb++) {
            int col = nb * 128 + tc * 4;
            float4 bv = *(const float4*)(ebias + col);
            float acc[4][4];
#pragma unroll
            for (int s = 0; s < 4; s++) {
                acc[s][0] = bv.x; acc[s][1] = bv.y; acc[s][2] = bv.z; acc[s][3] = bv.w;
            }
            for (int k = 0; k < PIN; k++) {
                float4 w = *(const float4*)(eW + (size_t)k * HID + col);
#pragma unroll
                for (int s = 0; s < 4; s++) {
                    float a = sp[(sg * 4 + s) * PIN + k];
                    acc[s][0] += a * w.x;
                    acc[s][1] += a * w.y;
                    acc[s][2] += a * w.z;
                    acc[s][3] += a * w.w;
                }
            }
#pragma unroll
            for (int s = 0; s < 4; s++) {
                int row = mb + sg * 4 + s;
                float* h = g_h0 + (size_t)row * HID + col;
                __half* th = g_ta0 + (size_t)row * HID + col;
                *(float4*)h = make_float4(acc[s][0], acc[s][1], acc[s][2], acc[s][3]);
                *(__half2*)(th)     = __floats2half2_rn(acc[s][0], acc[s][1]);
                *(__half2*)(th + 2) = __floats2half2_rn(acc[s][2], acc[s][3]);
            }
        }
        __threadfence();
        __syncthreads();
        if (tid == 0) atomicAdd(&g_eflag[ebk >> 2], 1);
        return;
    }

    // ---------------- role: gemm tile ----------------
    int gb = bid - PRE_BLKS;
    int l = gb >> 11;                        // 2048 tiles per layer
    int r = gb & 2047;
    int mblk = r >> 4, nblk = r & 15;
    int dir = l & 1;
    const float* bias = bias_all + (size_t)l * HID;

    const __half* __restrict__ Ah = dir ? g_ta1 : g_ta0;
    const __half* __restrict__ W  = g_wt + (size_t)l * HID * HID;

    uint32_t raw = smem_u32(dynsmem);
    uint32_t sbase = (raw + 1023u) & ~1023u;

    __shared__ float sbias[NT];
    __shared__ __align__(8) unsigned long long mbars[2 * NSTG];  // full[0..2], free[0..2]

    int mbase = mblk * MT, nbase = nblk * NT;
    if (tid < NT) sbias[tid] = bias[nbase + tid];

    uint32_t mb_full = smem_u32(&mbars[0]);
    uint32_t mb_free = smem_u32(&mbars[NSTG]);
    if (tid == 0) {
#pragma unroll
        for (int s = 0; s < NSTG; s++) {
            MBARRIER_INIT(mb_full + s * 8, NTHR);
            MBARRIER_INIT(mb_free + s * 8, 8);
        }
    }

    // dependencies: W^T of this layer; previous layer (or embed) for this m-block
    if (tid == 0) {
        while (atomicAdd(&g_wflag[l], 0) < 32) __nanosleep(64);
        if (l == 0) {
            while (atomicAdd(&g_eflag[mblk], 0) < 4) __nanosleep(64);
        } else {
            int* f = &g_flags[(l - 1) * MBLKS + mblk];
            while (atomicAdd(f, 0) < NBLKS) __nanosleep(64);
        }
        __threadfence();                 // acquire
    }
    __syncthreads();   // mbars + sbias + dependency visible

    int wid = tid >> 5, lane = tid & 31;
    int wm = wid & 1, wn = wid >> 1;          // 2 m-warps x 4 n-warps
    int g = lane >> 2, t = lane & 3;

    int rl  = lane & 7;
    int sec = lane >> 3;
    int hi_a = sec >> 1;
    int r8_a = sec & 1;
    int hi_b = sec & 1;
    int nfo_b = sec >> 1;

    uint32_t rowbase_a[4];
#pragma unroll
    for (int mf = 0; mf < 4; mf++)
        rowbase_a[mf] = (uint32_t)(wm * 64 + mf * 16 + r8_a * 8 + rl) * 128;
    uint32_t rowbase_b[2];
#pragma unroll
    for (int p = 0; p < 2; p++)
        rowbase_b[p] = (uint32_t)ABYTES
                     + (uint32_t)(wn * 32 + (2 * p + nfo_b) * 8 + rl) * 128;

    int lrow = tid >> 3, lcid = tid & 7;
    uint32_t aSmOff = (uint32_t)(lrow * 128 + ((lcid ^ (lrow & 7)) * 16));
    uint32_t bSmOff = (uint32_t)ABYTES + aSmOff;
    const __half* aG = Ah + (size_t)(mbase + lrow) * HID + lcid * 8;
    const __half* bG = W  + (size_t)(nbase + lrow) * HID + lcid * 8;

    const float* resb = (dir ? g_h1 : g_h0)
                      + (size_t)(mbase + (tid >> 1)) * HID + nbase + (tid & 1) * 64;

    auto load_chunk = [&](int c) {
        uint32_t sa = sbase + (uint32_t)(c % NSTG) * STGB;
        const __half* a = aG + c * KC;
        const __half* b = bG + c * KC;
#pragma unroll
        for (int i = 0; i < 4; i++) {
            cp_async16(sa + aSmOff + i * 4096, a + (size_t)i * 32 * HID);
            cp_async16(sa + bSmOff + i * 4096, b + (size_t)i * 32 * HID);
        }
    };

    float acc[4][4][4];
#pragma unroll
    for (int i = 0; i < 4; i++)
#pragma unroll
        for (int j = 0; j < 4; j++)
#pragma unroll
            for (int q = 0; q < 4; q++) acc[i][j][q] = 0.0f;

    uint32_t fa[2][4];
    uint32_t fb[2][8];

    auto ldfa = [&](uint32_t stb, int ks, int mf, int slot) {
        uint32_t offa = (uint32_t)((((2 * ks) | hi_a) ^ rl) * 16);
        LDSM4(fa[slot][0], fa[slot][1], fa[slot][2], fa[slot][3],
              stb + rowbase_a[mf] + offa);
    };
    auto ldfb = [&](uint32_t stb, int ks, int slot) {
        uint32_t offb = (uint32_t)((((2 * ks) | hi_b) ^ rl) * 16);
        LDSM4(fb[slot][0], fb[slot][1], fb[slot][2], fb[slot][3],
              stb + rowbase_b[0] + offb);
        LDSM4(fb[slot][4], fb[slot][5], fb[slot][6], fb[slot][7],
              stb + rowbase_b[1] + offb);
    };

    load_chunk(0);
    CPASYNC_MBAR_ARRIVE(mb_full + 0 * 8);
    load_chunk(1);
    CPASYNC_MBAR_ARRIVE(mb_full + 1 * 8);
    MBARRIER_WAIT_PARITY(mb_full + 0 * 8, 0);
    ldfa(sbase, 0, 0, 0);
    ldfb(sbase, 0, 0);

    for (int c = 0; c < NCH; c++) {
        int s = c % NSTG;
        uint32_t stb = sbase + (uint32_t)s * STGB;
        int s1 = (c + 1) % NSTG;
        uint32_t stb1 = sbase + (uint32_t)s1 * STGB;
        int p1 = ((c + 1) / NSTG) & 1;
        bool more = (c + 1 < NCH);

#pragma unroll
        for (int ks = 0; ks < 4; ks++) {
            int fbc = ks & 1;
            if (ks == 3 && more)
                MBARRIER_WAIT_PARITY(mb_full + s1 * 8, p1);
#pragma unroll
            for (int mf = 0; mf < 4; mf++) {
                int step = ks * 4 + mf;
                int p = step & 1;
                if (mf == 2) {
                    if (ks < 3) ldfb(stb, ks + 1, fbc ^ 1);
                    else if (more) ldfb(stb1, 0, 0);
                }
                if (step < 15)
                    ldfa(stb, (step + 1) >> 2, (step + 1) & 3, p ^ 1);
                else if (more)
                    ldfa(stb1, 0, 0, 0);
#pragma unroll
                for (int nf = 0; nf < 4; nf++)
                    mma_f16(acc[mf][nf], fa[p], &fb[fbc][nf * 2]);
            }
        }
        if (lane == 0) MBARRIER_ARRIVE(mb_free + s * 8);

        int nc = c + 2;
        if (nc < NCH) {
            int s2 = nc % NSTG;
            if (nc >= NSTG)
                MBARRIER_WAIT_PARITY_RELAXED(mb_free + s2 * 8, ((nc - NSTG) / NSTG) & 1);
            load_chunk(nc);
            CPASYNC_MBAR_ARRIVE(mb_full + s2 * 8);
        } else if (nc == NCH) {
            prefetch_l2(resb);
            prefetch_l2(resb + 32);
        }
    }

    // epilogue: bias + relu + residual
    const float* Abase = dir ? g_h1 : g_h0;
    float*       Cbase = dir ? g_h0 : g_h1;
    __half*      Chb   = dir ? g_ta0 : g_ta1;
    int mb0 = mbase + wm * 64, nb0 = nbase + wn * 32;
#pragma unroll
    for (int mf = 0; mf < 4; mf++) {
#pragma unroll
        for (int half = 0; half < 2; half++) {
            int row = mb0 + mf * 16 + half * 8 + g;
            const float* Ar = Abase + (size_t)row * HID + nb0;
            float* Cr = Cbase + (size_t)row * HID + nb0;
            __half* Chr = Chb + (size_t)row * HID + nb0;
#pragma unroll
            for (int nf = 0; nf < 4; nf++) {
                int cl = nf * 8 + 2 * t;
                float2 res = *(const float2*)(Ar + cl);
                float b0 = sbias[wn * 32 + cl];
                float b1 = sbias[wn * 32 + cl + 1];
                float v0 = acc[mf][nf][half * 2 + 0];
                float v1 = acc[mf][nf][half * 2 + 1];
                float2 o;
                o.x = res.x + fmaxf(v0 + b0, 0.0f);
                o.y = res.y + fmaxf(v1 + b1, 0.0f);
                *(float2*)(Cr + cl) = o;
                *(__half2*)(Chr + cl) = __floats2half2_rn(o.x, o.y);
            }
        }
    }

    // publish this tile (release: all threads fence, then sync, then count)
    __threadfence();
    __syncthreads();
    if (tid == 0) atomicAdd(&g_flags[l * MBLKS + mblk], 1);
}

// ============================================================
// Kernel 5: LayerNorm + head (N=4). One warp per row. Reads exact fp32.
// ============================================================
__global__ void __launch_bounds__(256) head_kernel(const float* __restrict__ lng,
                                                   const float* __restrict__ lnb,
                                                   const float* __restrict__ hW,
                                                   const float* __restrict__ hb,
                                                   float* __restrict__ out) {
    int w = threadIdx.x >> 5, lane = threadIdx.x & 31;
    int row = blockIdx.x * 8 + w;
    const float4* h4 = (const float4*)(g_h0 + (size_t)row * HID);
    float4 v[16];
    float s = 0.f, ss = 0.f;
#pragma unroll
    for (int i = 0; i < 16; i++) {
        v[i] = h4[i * 32 + lane];
        s += v[i].x + v[i].y + v[i].z + v[i].w;
        ss += v[i].x * v[i].x + v[i].y * v[i].y + v[i].z * v[i].z + v[i].w * v[i].w;
    }
#pragma unroll
    for (int off = 16; off; off >>= 1) {
        s += __shfl_xor_sync(0xffffffffu, s, off);
        ss += __shfl_xor_sync(0xffffffffu, ss, off);
    }
    float mu = s * (1.0f / HID);
    float var = ss * (1.0f / HID) - mu * mu;
    float rs = rsqrtf(var + 1e-5f);
    float a0 = 0.f, a1 = 0.f, a2 = 0.f, a3 = 0.f;
    const float4* g4 = (const float4*)lng;
    const float4* b4 = (const float4*)lnb;
    const float4* w4 = (const float4*)hW;
#pragma unroll 1
    for (int i = 0; i < 16; i++) {
        int k4 = i * 32 + lane;
        float4 gg = g4[k4], bb = b4[k4];
        float hn[4];
        hn[0] = (v[i].x - mu) * rs * gg.x + bb.x;
        hn[1] = (v[i].y - mu) * rs * gg.y + bb.y;
        hn[2] = (v[i].z - mu) * rs * gg.z + bb.z;
        hn[3] = (v[i].w - mu) * rs * gg.w + bb.w;
#pragma unroll
        for (int j = 0; j < 4; j++) {
            float4 wr = w4[k4 * 4 + j];
            a0 += hn[j] * wr.x;
            a1 += hn[j] * wr.y;
            a2 += hn[j] * wr.z;
            a3 += hn[j] * wr.w;
        }
    }
#pragma unroll
    for (int off = 16; off; off >>= 1) {
        a0 += __shfl_xor_sync(0xffffffffu, a0, off);
        a1 += __shfl_xor_sync(0xffffffffu, a1, off);
        a2 += __shfl_xor_sync(0xffffffffu, a2, off);
        a3 += __shfl_xor_sync(0xffffffffu, a3, off);
    }
    if (lane == 0) {
        float4 hbv = *(const float4*)hb;
        float4 o;
        o.x = a0 + hbv.x; o.y = a1 + hbv.y; o.z = a2 + hbv.z; o.w = a3 + hbv.w;
        ((float4*)out)[row] = o;
    }
}

// ============================================================
extern "C" void kernel_launch(void* const* d_in, const int* in_sizes, int n_in,
                              void* d_out, int out_size) {
    const float* x   = (const float*)d_in[0];
    const float* eW  = (const float*)d_in[1];
    const float* eb  = (const float*)d_in[2];
    const float* lW  = (const float*)d_in[3];
    const float* lb  = (const float*)d_in[4];
    const float* lng = (const float*)d_in[5];
    const float* lnb = (const float*)d_in[6];
    const float* hW  = (const float*)d_in[7];
    const float* hb  = (const float*)d_in[8];

    cudaFuncSetAttribute(mega_kernel, cudaFuncAttributeMaxDynamicSharedMemorySize, DYNSMEM);

    patch_kernel<<<BATCH / 8, 256>>>(x);
    mega_kernel<<<PRE_BLKS + NLAYER * MBLKS * NBLKS, NTHR, DYNSMEM>>>(eW, eb, lW, lb);
    head_kernel<<<BATCH / 8, 256>>>(lng, lnb, hW, hb, (float*)d_out);
}